// round 16
// baseline (speedup 1.0000x reference)
#include <cuda_runtime.h>
#include <cstdint>

#define BN 4
#define NN 2048
#define IND 128
#define NHEADS 4

// ---------------- scratch ----------------
__device__ float g_hcat[(size_t)BN * NN * 256];     // layer-1 h (tf32-rounded), [b][n][h*64+d]
__device__ float g_att1[(size_t)BN * NN * 256];     // layer-1 attention out (fp32)
__device__ float g_h2[(size_t)BN * NN * 64];        // layer-2 h (tf32-rounded)
__device__ float g_num2[(size_t)4 * BN * NN * 64];  // layer-2 split-K numerators
__device__ float g_den2[(size_t)4 * BN * NN];
__device__ uint32_t g_adjp[(size_t)BN * 64 * NN];   // bit-packed adjacency, TRANSPOSED [b][jword][i]

__device__ float g_Es1[NHEADS * BN * NN];
__device__ float g_Fs1[NHEADS * BN * NN];
__device__ float g_Et1[NHEADS * BN * NN];
__device__ float g_Ft1[NHEADS * BN * NN];
__device__ float g_Es2[BN * NN];
__device__ float g_Fs2[BN * NN];
__device__ float g_Et2[BN * NN];
__device__ float g_Ft2[BN * NN];

__device__ __forceinline__ float tf32r(float x) {
    uint32_t v;
    asm("cvt.rna.tf32.f32 %0, %1;" : "=r"(v) : "f"(x));
    return __uint_as_float(v);
}
__device__ __forceinline__ float warp_sum(float v) {
#pragma unroll
    for (int o = 16; o > 0; o >>= 1) v += __shfl_xor_sync(0xffffffffu, v, o);
    return v;
}
__device__ __forceinline__ void mma_tf32(float* c, uint32_t a0, uint32_t a1, uint32_t a2,
                                         uint32_t a3, uint32_t b0, uint32_t b1) {
    asm volatile(
        "mma.sync.aligned.m16n8k8.row.col.f32.tf32.tf32.f32 "
        "{%0,%1,%2,%3}, {%4,%5,%6,%7}, {%8,%9}, {%0,%1,%2,%3};"
        : "+f"(c[0]), "+f"(c[1]), "+f"(c[2]), "+f"(c[3])
        : "r"(a0), "r"(a1), "r"(a2), "r"(a3), "r"(b0), "r"(b1));
}

// ---------------- fused: proj1 (blocks 0..511) + pack_adj (blocks 512..2559) ----------------
#define PROJ1_BLOCKS (BN * NN / 16)   // 512
#define PACK_BLOCKS  2048

__global__ void fused_pack_proj1(const int* __restrict__ adj,
                                 const float* __restrict__ x,
                                 const float* __restrict__ W,
                                 const float* __restrict__ a) {
    __shared__ float xs[16][136];
    __shared__ float rs[16][8], rt[16][8];
    const int tid = threadIdx.x;

    if (blockIdx.x >= PROJ1_BLOCKS) {
        // ---------------- pack_adj path (no smem, no barrier) ----------------
        const int blk = blockIdx.x - PROJ1_BLOCKS;
        const int w = blk * 8 + (tid >> 5);
        const int lane = tid & 31;
        const int b = w >> 12;
        const int i = (w >> 1) & (NN - 1);
        const int half = w & 1;
        const int* src = adj + (size_t)w * 1024;
        int v[32];
#pragma unroll
        for (int u = 0; u < 32; ++u) v[u] = __ldg(&src[u * 32 + lane]);
        uint32_t mine = 0;
#pragma unroll
        for (int u = 0; u < 32; ++u) {
            uint32_t m = __ballot_sync(0xffffffffu, v[u] != 0);
            if (lane == u) mine = m;
        }
        g_adjp[((size_t)b * 64 + half * 32 + lane) * NN + i] = mine;
        return;
    }

    // ---------------- proj1 path (scalar, exact s/t) ----------------
    const int row0 = blockIdx.x * 16;

#pragma unroll
    for (int u = 0; u < 2; ++u) {
        int idx = tid + u * 256;
        int r = idx >> 5, c = (idx & 31) * 4;
        *(float4*)&xs[r][c] = *(const float4*)&x[(size_t)(row0 + r) * IND + c];
    }
    __syncthreads();

    const int h = tid >> 6, d = tid & 63;
    const float* Wc = W + (size_t)(h * IND) * 64 + d;
    float acc[16];
#pragma unroll
    for (int r = 0; r < 16; ++r) acc[r] = 0.f;
#pragma unroll 2
    for (int i = 0; i < IND; i += 4) {
        float w0 = Wc[(size_t)(i + 0) * 64];
        float w1 = Wc[(size_t)(i + 1) * 64];
        float w2 = Wc[(size_t)(i + 2) * 64];
        float w3 = Wc[(size_t)(i + 3) * 64];
#pragma unroll
        for (int r = 0; r < 16; ++r) {
            float4 xv = *(const float4*)&xs[r][i];
            acc[r] += xv.x * w0 + xv.y * w1 + xv.z * w2 + xv.w * w3;
        }
    }

    const float a1 = a[h * 128 + d];
    const float a2 = a[h * 128 + 64 + d];
    const int warp = tid >> 5, lane = tid & 31;
#pragma unroll
    for (int r = 0; r < 16; ++r) {
        g_hcat[(size_t)(row0 + r) * 256 + tid] = tf32r(acc[r]);
        float sp = warp_sum(acc[r] * a1);
        float tp = warp_sum(acc[r] * a2);
        if (lane == 0) { rs[r][warp] = sp; rt[r][warp] = tp; }
    }
    __syncthreads();
    if ((tid & 63) == 0) {
#pragma unroll
        for (int r = 0; r < 16; ++r) {
            float S = rs[r][2 * h] + rs[r][2 * h + 1];
            float T = rt[r][2 * h] + rt[r][2 * h + 1];
            size_t idx = (size_t)h * (BN * NN) + row0 + r;
            g_Es1[idx] = expf(S);
            g_Fs1[idx] = expf(0.2f * S);
            g_Et1[idx] = expf(T);
            g_Ft1[idx] = expf(0.2f * T);
        }
    }
}

// ---------------- proj2 (scalar, exact s/t): h2 = att1 @ W_out (tf32r) + exps ----------------
__global__ void proj2_kernel(const float* __restrict__ Wout,
                             const float* __restrict__ aout) {
    __shared__ float ys[16][260];
    __shared__ float part[4][16][64];
    __shared__ float rs[16][2], rt[16][2];
    const int row0 = blockIdx.x * 16;
    const int tid = threadIdx.x;

#pragma unroll
    for (int u = 0; u < 4; ++u) {
        int idx = tid + u * 256;
        int r = idx >> 6, c = (idx & 63) * 4;
        *(float4*)&ys[r][c] = *(const float4*)&g_att1[(size_t)(row0 + r) * 256 + c];
    }
    __syncthreads();

    const int p = tid >> 6, d = tid & 63;
    float acc[16];
#pragma unroll
    for (int r = 0; r < 16; ++r) acc[r] = 0.f;
#pragma unroll 2
    for (int i = 0; i < 64; i += 4) {
        float w0 = Wout[(size_t)(p * 64 + i + 0) * 64 + d];
        float w1 = Wout[(size_t)(p * 64 + i + 1) * 64 + d];
        float w2 = Wout[(size_t)(p * 64 + i + 2) * 64 + d];
        float w3 = Wout[(size_t)(p * 64 + i + 3) * 64 + d];
#pragma unroll
        for (int r = 0; r < 16; ++r) {
            float4 yv = *(const float4*)&ys[r][p * 64 + i];
            acc[r] += yv.x * w0 + yv.y * w1 + yv.z * w2 + yv.w * w3;
        }
    }
#pragma unroll
    for (int r = 0; r < 16; ++r) part[p][r][d] = acc[r];
    __syncthreads();

    {
        const float a1 = aout[d], a2 = aout[64 + d];
        const int warp = tid >> 5, lane = tid & 31;
#pragma unroll
        for (int rr = 0; rr < 4; ++rr) {
            const int r = p * 4 + rr;
            float v = part[0][r][d] + part[1][r][d] + part[2][r][d] + part[3][r][d];
            g_h2[(size_t)(row0 + r) * 64 + d] = tf32r(v);
            float sp = warp_sum(v * a1);
            float tp = warp_sum(v * a2);
            if (lane == 0) { rs[r][warp & 1] = sp; rt[r][warp & 1] = tp; }
        }
    }
    __syncthreads();
    if (tid < 16) {
        float S = rs[tid][0] + rs[tid][1];
        float T = rt[tid][0] + rt[tid][1];
        size_t idx = (size_t)(row0 + tid);
        g_Es2[idx] = expf(S);
        g_Fs2[idx] = expf(0.2f * S);
        g_Et2[idx] = expf(T);
        g_Ft2[idx] = expf(0.2f * T);
    }
}

// ---------------- tensor-core attention: K-split + double buffer, nb=8, FADD den ----------------
// 8 warps = 4 row-groups(32 rows) x 2 K-halves. One __syncthreads per 32-K tile.
// Denominator: FADD of rounded w in w-phase, shfl over 8 c4 lanes, atomicAdd to den_sh.
#define W_TILE_F 4608   // 128*36 floats
#define H_TILE_F 2304   // 32*72 floats
#define ATTN_SMEM_BYTES ((2 * W_TILE_F + 2 * H_TILE_F + 128) * 4)

template <int SPL, int L>
__global__ void __launch_bounds__(256, 2)
attn_m(void) {
    constexpr int HS = (L == 1) ? 256 : 64;
    extern __shared__ float dsm[];
    float* const wbuf0 = dsm;
    float* const wbuf1 = dsm + W_TILE_F;
    float* const hbuf0 = dsm + 2 * W_TILE_F;
    float* const hbuf1 = dsm + 2 * W_TILE_F + H_TILE_F;
    float* const den_sh = dsm + 2 * W_TILE_F + 2 * H_TILE_F;

    const int tid = threadIdx.x;
    const int wid = tid >> 5, lane = tid & 31;
    const int lx = lane & 3, ly = lane >> 2;
    const int wg = wid >> 1, kg = wid & 1;
    const int b = blockIdx.z;
    const int head = (L == 1) ? blockIdx.y : 0;
    const int split = (L == 1) ? 0 : blockIdx.y;
    const int i0 = blockIdx.x * 128;
    const size_t ebase = ((L == 1) ? ((size_t)head * BN + b) : (size_t)b) * NN;

    const float* __restrict__ Es = (L == 1) ? g_Es1 : g_Es2;
    const float* __restrict__ Fs = (L == 1) ? g_Fs1 : g_Fs2;
    const float* __restrict__ Et = (L == 1) ? g_Et1 : g_Et2;
    const float* __restrict__ Ft = (L == 1) ? g_Ft1 : g_Ft2;
    const float* __restrict__ hb = (L == 1) ? (g_hcat + (size_t)b * NN * 256 + head * 64)
                                            : (g_h2 + (size_t)b * NN * 64);
    const uint32_t* __restrict__ adjpT = g_adjp + (size_t)b * 64 * NN;

    if (tid < 128) den_sh[tid] = 0.f;

    const int c4 = tid & 7;
    const int rw = tid >> 3;
    const float4 es4 = *(const float4*)&Es[ebase + i0 + rw * 4];
    const float4 fs4 = *(const float4*)&Fs[ebase + i0 + rw * 4];
    const float esr[4] = {es4.x, es4.y, es4.z, es4.w};
    const float fsr[4] = {fs4.x, fs4.y, fs4.z, fs4.w};
    float denp[4] = {0.f, 0.f, 0.f, 0.f};

    const int hj = tid >> 4, hd = (tid & 15) * 4;

    float4 c_[2][8];
#pragma unroll
    for (int rb = 0; rb < 2; ++rb)
#pragma unroll
        for (int nb = 0; nb < 8; ++nb) c_[rb][nb] = make_float4(0.f, 0.f, 0.f, 0.f);

    constexpr int KSPAN = NN / SPL;
    constexpr int NT = KSPAN / 32;           // even for both layers
    const int jb = split * KSPAN;

    // prefetch registers for tile 0
    int4 pm;
    float4 pe, pf, ph0, ph1;
    {
        const int j0 = jb;
        pm = *(const int4*)&adjpT[(size_t)(j0 >> 5) * NN + i0 + rw * 4];
        pe = *(const float4*)&Et[ebase + j0 + c4 * 4];
        pf = *(const float4*)&Ft[ebase + j0 + c4 * 4];
        ph0 = *(const float4*)&hb[(size_t)(j0 + hj) * HS + hd];
        ph1 = *(const float4*)&hb[(size_t)(j0 + hj + 16) * HS + hd];
    }

    // one tile body: w-phase+stage -> BAR -> prefetch(t+1) -> MMA(t)
    auto tile_body = [&](float* __restrict__ wsh, float* __restrict__ hsh, int t) {
        // ---- w-phase(t) from prefetched regs ----
        {
            const float e[4] = {pe.x, pe.y, pe.z, pe.w};
            const float f[4] = {pf.x, pf.y, pf.z, pf.w};
            const uint32_t mw[4] = {(uint32_t)pm.x, (uint32_t)pm.y,
                                    (uint32_t)pm.z, (uint32_t)pm.w};
#pragma unroll
            for (int k = 0; k < 4; ++k) {
                const uint32_t m = mw[k] >> (c4 * 4);
                float wq[4];
#pragma unroll
                for (int q = 0; q < 4; ++q) {
                    float w = fmaxf(esr[k] * e[q], fsr[k] * f[q]);
                    w = ((m >> q) & 1u) ? w : 0.f;
                    float wr = tf32r(w);
                    denp[k] += wr;
                    wq[q] = wr;
                }
                *(float4*)&wsh[(rw * 4 + k) * 36 + c4 * 4] =
                    make_float4(wq[0], wq[1], wq[2], wq[3]);
            }
        }
        *(float4*)&hsh[hj * 72 + hd] = ph0;
        *(float4*)&hsh[(hj + 16) * 72 + hd] = ph1;

        __syncthreads();   // the ONLY barrier per tile

        // ---- prefetch tile t+1 ----
        if (t + 1 < NT) {
            const int j0 = jb + (t + 1) * 32;
            pm = *(const int4*)&adjpT[(size_t)(j0 >> 5) * NN + i0 + rw * 4];
            pe = *(const float4*)&Et[ebase + j0 + c4 * 4];
            pf = *(const float4*)&Ft[ebase + j0 + c4 * 4];
            ph0 = *(const float4*)&hb[(size_t)(j0 + hj) * HS + hd];
            ph1 = *(const float4*)&hb[(size_t)(j0 + hj + 16) * HS + hd];
        }

        // ---- MMA(t): this warp's K half ----
        const int r0 = wg * 32 + ly;
#pragma unroll
        for (int kk2 = 0; kk2 < 2; ++kk2) {
            const int kc = (kg * 2 + kk2) * 8;
            uint32_t a[2][4];
#pragma unroll
            for (int rb = 0; rb < 2; ++rb) {
                a[rb][0] = __float_as_uint(wsh[(r0 + rb * 16) * 36 + kc + lx]);
                a[rb][1] = __float_as_uint(wsh[(r0 + rb * 16 + 8) * 36 + kc + lx]);
                a[rb][2] = __float_as_uint(wsh[(r0 + rb * 16) * 36 + kc + lx + 4]);
                a[rb][3] = __float_as_uint(wsh[(r0 + rb * 16 + 8) * 36 + kc + lx + 4]);
            }
#pragma unroll
            for (int nb = 0; nb < 8; ++nb) {
                uint32_t b0 = __float_as_uint(hsh[(kc + lx) * 72 + nb * 8 + ly]);
                uint32_t b1 = __float_as_uint(hsh[(kc + lx + 4) * 72 + nb * 8 + ly]);
                mma_tf32((float*)&c_[0][nb], a[0][0], a[0][1], a[0][2], a[0][3], b0, b1);
                mma_tf32((float*)&c_[1][nb], a[1][0], a[1][1], a[1][2], a[1][3], b0, b1);
            }
        }
    };

    for (int t = 0; t < NT; t += 2) {
        tile_body(wbuf0, hbuf0, t);
        tile_body(wbuf1, hbuf1, t + 1);
    }

    // ---- denominator: shfl-reduce over 8 c4 lanes, one atomicAdd per row ----
#pragma unroll
    for (int k = 0; k < 4; ++k) {
        denp[k] += __shfl_xor_sync(0xffffffffu, denp[k], 1);
        denp[k] += __shfl_xor_sync(0xffffffffu, denp[k], 2);
        denp[k] += __shfl_xor_sync(0xffffffffu, denp[k], 4);
    }
    if (c4 == 0) {
#pragma unroll
        for (int k = 0; k < 4; ++k) atomicAdd(&den_sh[rw * 4 + k], denp[k]);
    }

    // ---- merge K-half partials (kg=1 -> kg=0) via wbuf0 scratch, 2 passes ----
    float* mbuf = wbuf0;
#pragma unroll
    for (int pass = 0; pass < 2; ++pass) {
        __syncthreads();
        if (kg == 1) {
            float4* p = (float4*)(mbuf + (wg * 32 + lane) * 32);
#pragma unroll
            for (int rb = 0; rb < 2; ++rb)
#pragma unroll
                for (int q = 0; q < 4; ++q) p[rb * 4 + q] = c_[rb][pass * 4 + q];
        }
        __syncthreads();
        if (kg == 0) {
            const float4* p = (const float4*)(mbuf + (wg * 32 + lane) * 32);
#pragma unroll
            for (int rb = 0; rb < 2; ++rb)
#pragma unroll
                for (int q = 0; q < 4; ++q) {
                    float4 v = p[rb * 4 + q];
                    c_[rb][pass * 4 + q].x += v.x;
                    c_[rb][pass * 4 + q].y += v.y;
                    c_[rb][pass * 4 + q].z += v.z;
                    c_[rb][pass * 4 + q].w += v.w;
                }
        }
    }
    __syncthreads();   // den_sh atomics + merge all visible

    // ---- epilogue (kg==0 warps own merged sums; den from den_sh) ----
    if (kg == 0) {
#pragma unroll
        for (int rb = 0; rb < 2; ++rb) {
            const int r0 = wg * 32 + rb * 16 + ly;
            const float den0 = den_sh[r0];
            const float den1 = den_sh[r0 + 8];
            if (L == 1) {
                const float inv0 = 1.0f / den0;
                const float inv1 = 1.0f / den1;
                float* o0 = g_att1 + ((size_t)b * NN + i0 + r0) * 256 + head * 64;
                float* o1 = o0 + 8 * 256;
#pragma unroll
                for (int nb = 0; nb < 8; ++nb) {
                    const int col = nb * 8 + 2 * lx;
                    *(float2*)(o0 + col) = make_float2(c_[rb][nb].x * inv0, c_[rb][nb].y * inv0);
                    *(float2*)(o1 + col) = make_float2(c_[rb][nb].z * inv1, c_[rb][nb].w * inv1);
                }
            } else {
                float* nbase = g_num2 + ((size_t)split * BN + b) * NN * 64;
                float* o0 = nbase + (size_t)(i0 + r0) * 64;
                float* o1 = o0 + 8 * 64;
#pragma unroll
                for (int nb = 0; nb < 8; ++nb) {
                    const int col = nb * 8 + 2 * lx;
                    *(float2*)(o0 + col) = make_float2(c_[rb][nb].x, c_[rb][nb].y);
                    *(float2*)(o1 + col) = make_float2(c_[rb][nb].z, c_[rb][nb].w);
                }
                if (lx == 0) {
                    float* dbase = g_den2 + ((size_t)split * BN + b) * NN;
                    dbase[i0 + r0] = den0;
                    dbase[i0 + r0 + 8] = den1;
                }
            }
        }
    }
}

// ---------------- layer-2 split-K combine ----------------
__global__ void combine2_kernel(float* __restrict__ out) {
    size_t idx = (size_t)blockIdx.x * 256 + threadIdx.x;
    size_t row = idx >> 4;
    int c = (int)(idx & 15) * 4;
    float den = 0.f;
    float4 n = make_float4(0.f, 0.f, 0.f, 0.f);
#pragma unroll
    for (int s = 0; s < 4; ++s) {
        den += g_den2[(size_t)s * BN * NN + row];
        float4 p = *(const float4*)&g_num2[((size_t)s * BN * NN + row) * 64 + c];
        n.x += p.x; n.y += p.y; n.z += p.z; n.w += p.w;
    }
    float inv = 1.0f / den;
    *(float4*)&out[row * 64 + c] = make_float4(n.x * inv, n.y * inv, n.z * inv, n.w * inv);
}

extern "C" void kernel_launch(void* const* d_in, const int* in_sizes, int n_in,
                              void* d_out, int out_size) {
    const float* x   = (const float*)d_in[0];
    const int*   adj = (const int*)  d_in[1];
    const float* Wh  = (const float*)d_in[2];
    const float* ah  = (const float*)d_in[3];
    const float* Wo  = (const float*)d_in[4];
    const float* ao  = (const float*)d_in[5];
    float* out = (float*)d_out;

    cudaFuncSetAttribute(attn_m<1, 1>, cudaFuncAttributeMaxDynamicSharedMemorySize,
                         ATTN_SMEM_BYTES);
    cudaFuncSetAttribute(attn_m<4, 2>, cudaFuncAttributeMaxDynamicSharedMemorySize,
                         ATTN_SMEM_BYTES);

    fused_pack_proj1<<<PROJ1_BLOCKS + PACK_BLOCKS, 256>>>(adj, x, Wh, ah);
    attn_m<1, 1><<<dim3(NN / 128, NHEADS, BN), 256, ATTN_SMEM_BYTES>>>();
    proj2_kernel<<<BN * NN / 16, 256>>>(Wo, ao);
    attn_m<4, 2><<<dim3(NN / 128, 4, BN), 256, ATTN_SMEM_BYTES>>>();
    combine2_kernel<<<BN * NN * 16 / 256, 256>>>(out);
}

// round 17
// speedup vs baseline: 1.1741x; 1.1741x over previous
#include <cuda_runtime.h>
#include <cstdint>

#define BN 4
#define NN 2048
#define IND 128
#define NHEADS 4

// ---------------- scratch ----------------
__device__ float g_hcat[(size_t)BN * NN * 256];     // layer-1 h (tf32-rounded), [b][n][h*64+d]
__device__ float g_att1[(size_t)BN * NN * 256];     // layer-1 attention out (fp32)
__device__ float g_h2[(size_t)BN * NN * 64];        // layer-2 h (tf32-rounded)
__device__ float g_num2[(size_t)4 * BN * NN * 64];  // layer-2 split-K numerators
__device__ float g_den2[(size_t)4 * BN * NN];
__device__ uint32_t g_adjp[(size_t)BN * 64 * NN];   // bit-packed adjacency, TRANSPOSED [b][jword][i]

__device__ float g_Es1[NHEADS * BN * NN];
__device__ float g_Fs1[NHEADS * BN * NN];
__device__ float g_Et1[NHEADS * BN * NN];
__device__ float g_Ft1[NHEADS * BN * NN];
__device__ float g_Es2[BN * NN];
__device__ float g_Fs2[BN * NN];
__device__ float g_Et2[BN * NN];
__device__ float g_Ft2[BN * NN];

__device__ __forceinline__ float tf32r(float x) {
    uint32_t v;
    asm("cvt.rna.tf32.f32 %0, %1;" : "=r"(v) : "f"(x));
    return __uint_as_float(v);
}
__device__ __forceinline__ float warp_sum(float v) {
#pragma unroll
    for (int o = 16; o > 0; o >>= 1) v += __shfl_xor_sync(0xffffffffu, v, o);
    return v;
}
__device__ __forceinline__ void mma_tf32(float* c, uint32_t a0, uint32_t a1, uint32_t a2,
                                         uint32_t a3, uint32_t b0, uint32_t b1) {
    asm volatile(
        "mma.sync.aligned.m16n8k8.row.col.f32.tf32.tf32.f32 "
        "{%0,%1,%2,%3}, {%4,%5,%6,%7}, {%8,%9}, {%0,%1,%2,%3};"
        : "+f"(c[0]), "+f"(c[1]), "+f"(c[2]), "+f"(c[3])
        : "r"(a0), "r"(a1), "r"(a2), "r"(a3), "r"(b0), "r"(b1));
}

// ---------------- fused: proj1 (blocks 0..511) + pack_adj (blocks 512..2559) ----------------
// Independent workloads with complementary bottlenecks; fused to overlap in one wave set.
#define PROJ1_BLOCKS (BN * NN / 16)   // 512
#define PACK_BLOCKS  2048

__global__ void fused_pack_proj1(const int* __restrict__ adj,
                                 const float* __restrict__ x,
                                 const float* __restrict__ W,
                                 const float* __restrict__ a) {
    __shared__ float xs[16][136];
    __shared__ float rs[16][8], rt[16][8];
    const int tid = threadIdx.x;

    if (blockIdx.x >= PROJ1_BLOCKS) {
        // ---------------- pack_adj path (no smem, no barrier) ----------------
        const int blk = blockIdx.x - PROJ1_BLOCKS;
        const int w = blk * 8 + (tid >> 5);
        const int lane = tid & 31;
        const int b = w >> 12;
        const int i = (w >> 1) & (NN - 1);
        const int half = w & 1;
        const int* src = adj + (size_t)w * 1024;
        int v[32];
#pragma unroll
        for (int u = 0; u < 32; ++u) v[u] = __ldg(&src[u * 32 + lane]);
        uint32_t mine = 0;
#pragma unroll
        for (int u = 0; u < 32; ++u) {
            uint32_t m = __ballot_sync(0xffffffffu, v[u] != 0);
            if (lane == u) mine = m;
        }
        g_adjp[((size_t)b * 64 + half * 32 + lane) * NN + i] = mine;
        return;
    }

    // ---------------- proj1 path (scalar, exact s/t) ----------------
    const int row0 = blockIdx.x * 16;

#pragma unroll
    for (int u = 0; u < 2; ++u) {
        int idx = tid + u * 256;
        int r = idx >> 5, c = (idx & 31) * 4;
        *(float4*)&xs[r][c] = *(const float4*)&x[(size_t)(row0 + r) * IND + c];
    }
    __syncthreads();

    const int h = tid >> 6, d = tid & 63;
    const float* Wc = W + (size_t)(h * IND) * 64 + d;
    float acc[16];
#pragma unroll
    for (int r = 0; r < 16; ++r) acc[r] = 0.f;
#pragma unroll 2
    for (int i = 0; i < IND; i += 4) {
        float w0 = Wc[(size_t)(i + 0) * 64];
        float w1 = Wc[(size_t)(i + 1) * 64];
        float w2 = Wc[(size_t)(i + 2) * 64];
        float w3 = Wc[(size_t)(i + 3) * 64];
#pragma unroll
        for (int r = 0; r < 16; ++r) {
            float4 xv = *(const float4*)&xs[r][i];
            acc[r] += xv.x * w0 + xv.y * w1 + xv.z * w2 + xv.w * w3;
        }
    }

    const float a1 = a[h * 128 + d];
    const float a2 = a[h * 128 + 64 + d];
    const int warp = tid >> 5, lane = tid & 31;
#pragma unroll
    for (int r = 0; r < 16; ++r) {
        g_hcat[(size_t)(row0 + r) * 256 + tid] = tf32r(acc[r]);
        float sp = warp_sum(acc[r] * a1);
        float tp = warp_sum(acc[r] * a2);
        if (lane == 0) { rs[r][warp] = sp; rt[r][warp] = tp; }
    }
    __syncthreads();
    if ((tid & 63) == 0) {
#pragma unroll
        for (int r = 0; r < 16; ++r) {
            float S = rs[r][2 * h] + rs[r][2 * h + 1];
            float T = rt[r][2 * h] + rt[r][2 * h + 1];
            size_t idx = (size_t)h * (BN * NN) + row0 + r;
            g_Es1[idx] = expf(S);
            g_Fs1[idx] = expf(0.2f * S);
            g_Et1[idx] = expf(T);
            g_Ft1[idx] = expf(0.2f * T);
        }
    }
}

// ---------------- proj2 (scalar, exact s/t): h2 = att1 @ W_out (tf32r) + exps ----------------
// Phase 2 parallelized: group p handles rows 4p..4p+3 (same per-row arithmetic/order).
__global__ void proj2_kernel(const float* __restrict__ Wout,
                             const float* __restrict__ aout) {
    __shared__ float ys[16][260];
    __shared__ float part[4][16][64];
    __shared__ float rs[16][2], rt[16][2];
    const int row0 = blockIdx.x * 16;
    const int tid = threadIdx.x;

#pragma unroll
    for (int u = 0; u < 4; ++u) {
        int idx = tid + u * 256;
        int r = idx >> 6, c = (idx & 63) * 4;
        *(float4*)&ys[r][c] = *(const float4*)&g_att1[(size_t)(row0 + r) * 256 + c];
    }
    __syncthreads();

    const int p = tid >> 6, d = tid & 63;
    float acc[16];
#pragma unroll
    for (int r = 0; r < 16; ++r) acc[r] = 0.f;
#pragma unroll 2
    for (int i = 0; i < 64; i += 4) {
        float w0 = Wout[(size_t)(p * 64 + i + 0) * 64 + d];
        float w1 = Wout[(size_t)(p * 64 + i + 1) * 64 + d];
        float w2 = Wout[(size_t)(p * 64 + i + 2) * 64 + d];
        float w3 = Wout[(size_t)(p * 64 + i + 3) * 64 + d];
#pragma unroll
        for (int r = 0; r < 16; ++r) {
            float4 yv = *(const float4*)&ys[r][p * 64 + i];
            acc[r] += yv.x * w0 + yv.y * w1 + yv.z * w2 + yv.w * w3;
        }
    }
#pragma unroll
    for (int r = 0; r < 16; ++r) part[p][r][d] = acc[r];
    __syncthreads();

    {
        const float a1 = aout[d], a2 = aout[64 + d];
        const int warp = tid >> 5, lane = tid & 31;
#pragma unroll
        for (int rr = 0; rr < 4; ++rr) {
            const int r = p * 4 + rr;
            float v = part[0][r][d] + part[1][r][d] + part[2][r][d] + part[3][r][d];
            g_h2[(size_t)(row0 + r) * 64 + d] = tf32r(v);
            float sp = warp_sum(v * a1);
            float tp = warp_sum(v * a2);
            if (lane == 0) { rs[r][warp & 1] = sp; rt[r][warp & 1] = tp; }
        }
    }
    __syncthreads();
    if (tid < 16) {
        float S = rs[tid][0] + rs[tid][1];
        float T = rt[tid][0] + rt[tid][1];
        size_t idx = (size_t)(row0 + tid);
        g_Es2[idx] = expf(S);
        g_Fs2[idx] = expf(0.2f * S);
        g_Et2[idx] = expf(T);
        g_Ft2[idx] = expf(0.2f * T);
    }
}

// ---------------- tensor-core attention: K-split warps + TRUE double buffer ----------------
// 8 warps = 4 row-groups(32 rows) x 2 K-halves. One __syncthreads per 32-K tile.
// B tile 9 n-blocks: cols 0..63 = h, col 64 = ones (denominator), 65..71 = 0.
// w stored RAW fp32 (no cvt): HMMA truncates num and den identically -> ratio bias cancels.
#define W_TILE_F 4608   // 128*36 floats
#define H_TILE_F 2304   // 32*72 floats
#define ATTN_SMEM_BYTES ((2 * W_TILE_F + 2 * H_TILE_F) * 4)

template <int SPL, int L>
__global__ void __launch_bounds__(256, 2)
attn_m(void) {
    constexpr int HS = (L == 1) ? 256 : 64;
    extern __shared__ float dsm[];
    float* const wbuf0 = dsm;
    float* const wbuf1 = dsm + W_TILE_F;
    float* const hbuf0 = dsm + 2 * W_TILE_F;
    float* const hbuf1 = dsm + 2 * W_TILE_F + H_TILE_F;

    const int tid = threadIdx.x;
    const int wid = tid >> 5, lane = tid & 31;
    const int lx = lane & 3, ly = lane >> 2;
    const int wg = wid >> 1, kg = wid & 1;
    const int b = blockIdx.z;
    const int head = (L == 1) ? blockIdx.y : 0;
    const int split = (L == 1) ? 0 : blockIdx.y;
    const int i0 = blockIdx.x * 128;
    const size_t ebase = ((L == 1) ? ((size_t)head * BN + b) : (size_t)b) * NN;

    const float* __restrict__ Es = (L == 1) ? g_Es1 : g_Es2;
    const float* __restrict__ Fs = (L == 1) ? g_Fs1 : g_Fs2;
    const float* __restrict__ Et = (L == 1) ? g_Et1 : g_Et2;
    const float* __restrict__ Ft = (L == 1) ? g_Ft1 : g_Ft2;
    const float* __restrict__ hb = (L == 1) ? (g_hcat + (size_t)b * NN * 256 + head * 64)
                                            : (g_h2 + (size_t)b * NN * 64);
    const uint32_t* __restrict__ adjpT = g_adjp + (size_t)b * 64 * NN;

    // ones column (64) / zeros (65..71) in BOTH h buffers; never overwritten.
    if (tid < 64) {
        float* hrow = ((tid & 32) ? hbuf1 : hbuf0) + (tid & 31) * 72;
        hrow[64] = 1.0f;
#pragma unroll
        for (int q = 1; q < 8; ++q) hrow[64 + q] = 0.f;
    }

    const int c4 = tid & 7;
    const int rw = tid >> 3;
    const float4 es4 = *(const float4*)&Es[ebase + i0 + rw * 4];
    const float4 fs4 = *(const float4*)&Fs[ebase + i0 + rw * 4];
    const float esr[4] = {es4.x, es4.y, es4.z, es4.w};
    const float fsr[4] = {fs4.x, fs4.y, fs4.z, fs4.w};

    const int hj = tid >> 4, hd = (tid & 15) * 4;

    float4 c_[2][9];
#pragma unroll
    for (int rb = 0; rb < 2; ++rb)
#pragma unroll
        for (int nb = 0; nb < 9; ++nb) c_[rb][nb] = make_float4(0.f, 0.f, 0.f, 0.f);

    constexpr int KSPAN = NN / SPL;
    constexpr int NT = KSPAN / 32;           // even for both layers
    const int jb = split * KSPAN;

    // prefetch registers for tile 0
    int4 pm;
    float4 pe, pf, ph0, ph1;
    {
        const int j0 = jb;
        pm = *(const int4*)&adjpT[(size_t)(j0 >> 5) * NN + i0 + rw * 4];
        pe = *(const float4*)&Et[ebase + j0 + c4 * 4];
        pf = *(const float4*)&Ft[ebase + j0 + c4 * 4];
        ph0 = *(const float4*)&hb[(size_t)(j0 + hj) * HS + hd];
        ph1 = *(const float4*)&hb[(size_t)(j0 + hj + 16) * HS + hd];
    }

    // one tile body: w-phase+stage -> BAR -> prefetch(t+1) -> MMA(t)
    auto tile_body = [&](float* __restrict__ wsh, float* __restrict__ hsh, int t) {
        // ---- w-phase(t) from prefetched regs (raw fp32 w; HMMA truncates) ----
        {
            const float e[4] = {pe.x, pe.y, pe.z, pe.w};
            const float f[4] = {pf.x, pf.y, pf.z, pf.w};
            const uint32_t mw[4] = {(uint32_t)pm.x, (uint32_t)pm.y,
                                    (uint32_t)pm.z, (uint32_t)pm.w};
#pragma unroll
            for (int k = 0; k < 4; ++k) {
                const uint32_t m = mw[k] >> (c4 * 4);
                float wq[4];
#pragma unroll
                for (int q = 0; q < 4; ++q) {
                    float w = fmaxf(esr[k] * e[q], fsr[k] * f[q]);
                    wq[q] = ((m >> q) & 1u) ? w : 0.f;
                }
                *(float4*)&wsh[(rw * 4 + k) * 36 + c4 * 4] =
                    make_float4(wq[0], wq[1], wq[2], wq[3]);
            }
        }
        *(float4*)&hsh[hj * 72 + hd] = ph0;
        *(float4*)&hsh[(hj + 16) * 72 + hd] = ph1;

        __syncthreads();   // the ONLY barrier per tile

        // ---- prefetch tile t+1 ----
        if (t + 1 < NT) {
            const int j0 = jb + (t + 1) * 32;
            pm = *(const int4*)&adjpT[(size_t)(j0 >> 5) * NN + i0 + rw * 4];
            pe = *(const float4*)&Et[ebase + j0 + c4 * 4];
            pf = *(const float4*)&Ft[ebase + j0 + c4 * 4];
            ph0 = *(const float4*)&hb[(size_t)(j0 + hj) * HS + hd];
            ph1 = *(const float4*)&hb[(size_t)(j0 + hj + 16) * HS + hd];
        }

        // ---- MMA(t): this warp's K half ----
        const int r0 = wg * 32 + ly;
#pragma unroll
        for (int kk2 = 0; kk2 < 2; ++kk2) {
            const int kc = (kg * 2 + kk2) * 8;
            uint32_t a[2][4];
#pragma unroll
            for (int rb = 0; rb < 2; ++rb) {
                a[rb][0] = __float_as_uint(wsh[(r0 + rb * 16) * 36 + kc + lx]);
                a[rb][1] = __float_as_uint(wsh[(r0 + rb * 16 + 8) * 36 + kc + lx]);
                a[rb][2] = __float_as_uint(wsh[(r0 + rb * 16) * 36 + kc + lx + 4]);
                a[rb][3] = __float_as_uint(wsh[(r0 + rb * 16 + 8) * 36 + kc + lx + 4]);
            }
#pragma unroll
            for (int nb = 0; nb < 9; ++nb) {
                uint32_t b0 = __float_as_uint(hsh[(kc + lx) * 72 + nb * 8 + ly]);
                uint32_t b1 = __float_as_uint(hsh[(kc + lx + 4) * 72 + nb * 8 + ly]);
                mma_tf32((float*)&c_[0][nb], a[0][0], a[0][1], a[0][2], a[0][3], b0, b1);
                mma_tf32((float*)&c_[1][nb], a[1][0], a[1][1], a[1][2], a[1][3], b0, b1);
            }
        }
    };

    for (int t = 0; t < NT; t += 2) {
        tile_body(wbuf0, hbuf0, t);
        tile_body(wbuf1, hbuf1, t + 1);
    }

    // ---- merge K-half partials (kg=1 -> kg=0) via wbuf0 scratch, 3 passes ----
    float* mbuf = wbuf0;
#pragma unroll
    for (int pass = 0; pass < 3; ++pass) {
        __syncthreads();
        if (kg == 1) {
            float4* p = (float4*)(mbuf + (wg * 32 + lane) * 24);
#pragma unroll
            for (int rb = 0; rb < 2; ++rb)
#pragma unroll
                for (int q = 0; q < 3; ++q) p[rb * 3 + q] = c_[rb][pass * 3 + q];
        }
        __syncthreads();
        if (kg == 0) {
            const float4* p = (const float4*)(mbuf + (wg * 32 + lane) * 24);
#pragma unroll
            for (int rb = 0; rb < 2; ++rb)
#pragma unroll
                for (int q = 0; q < 3; ++q) {
                    float4 v = p[rb * 3 + q];
                    c_[rb][pass * 3 + q].x += v.x;
                    c_[rb][pass * 3 + q].y += v.y;
                    c_[rb][pass * 3 + q].z += v.z;
                    c_[rb][pass * 3 + q].w += v.w;
                }
        }
    }

    // ---- epilogue (kg==0 warps; den = nb-8 col 64, lane ly*4) ----
    if (kg == 0) {
#pragma unroll
        for (int rb = 0; rb < 2; ++rb) {
            const int r0 = wg * 32 + rb * 16 + ly;
            const float den0 = __shfl_sync(0xffffffffu, c_[rb][8].x, ly * 4);
            const float den1 = __shfl_sync(0xffffffffu, c_[rb][8].z, ly * 4);
            if (L == 1) {
                const float inv0 = 1.0f / den0;
                const float inv1 = 1.0f / den1;
                float* o0 = g_att1 + ((size_t)b * NN + i0 + r0) * 256 + head * 64;
                float* o1 = o0 + 8 * 256;
#pragma unroll
                for (int nb = 0; nb < 8; ++nb) {
                    const int col = nb * 8 + 2 * lx;
                    *(float2*)(o0 + col) = make_float2(c_[rb][nb].x * inv0, c_[rb][nb].y * inv0);
                    *(float2*)(o1 + col) = make_float2(c_[rb][nb].z * inv1, c_[rb][nb].w * inv1);
                }
            } else {
                float* nbase = g_num2 + ((size_t)split * BN + b) * NN * 64;
                float* o0 = nbase + (size_t)(i0 + r0) * 64;
                float* o1 = o0 + 8 * 64;
#pragma unroll
                for (int nb = 0; nb < 8; ++nb) {
                    const int col = nb * 8 + 2 * lx;
                    *(float2*)(o0 + col) = make_float2(c_[rb][nb].x, c_[rb][nb].y);
                    *(float2*)(o1 + col) = make_float2(c_[rb][nb].z, c_[rb][nb].w);
                }
                if (lx == 0) {
                    float* dbase = g_den2 + ((size_t)split * BN + b) * NN;
                    dbase[i0 + r0] = c_[rb][8].x;
                    dbase[i0 + r0 + 8] = c_[rb][8].z;
                }
            }
        }
    }
}

// ---------------- layer-2 split-K combine ----------------
__global__ void combine2_kernel(float* __restrict__ out) {
    size_t idx = (size_t)blockIdx.x * 256 + threadIdx.x;
    size_t row = idx >> 4;
    int c = (int)(idx & 15) * 4;
    float den = 0.f;
    float4 n = make_float4(0.f, 0.f, 0.f, 0.f);
#pragma unroll
    for (int s = 0; s < 4; ++s) {
        den += g_den2[(size_t)s * BN * NN + row];
        float4 p = *(const float4*)&g_num2[((size_t)s * BN * NN + row) * 64 + c];
        n.x += p.x; n.y += p.y; n.z += p.z; n.w += p.w;
    }
    float inv = 1.0f / den;
    *(float4*)&out[row * 64 + c] = make_float4(n.x * inv, n.y * inv, n.z * inv, n.w * inv);
}

extern "C" void kernel_launch(void* const* d_in, const int* in_sizes, int n_in,
                              void* d_out, int out_size) {
    const float* x   = (const float*)d_in[0];
    const int*   adj = (const int*)  d_in[1];
    const float* Wh  = (const float*)d_in[2];
    const float* ah  = (const float*)d_in[3];
    const float* Wo  = (const float*)d_in[4];
    const float* ao  = (const float*)d_in[5];
    float* out = (float*)d_out;

    cudaFuncSetAttribute(attn_m<1, 1>, cudaFuncAttributeMaxDynamicSharedMemorySize,
                         ATTN_SMEM_BYTES);
    cudaFuncSetAttribute(attn_m<4, 2>, cudaFuncAttributeMaxDynamicSharedMemorySize,
                         ATTN_SMEM_BYTES);

    fused_pack_proj1<<<PROJ1_BLOCKS + PACK_BLOCKS, 256>>>(adj, x, Wh, ah);
    attn_m<1, 1><<<dim3(NN / 128, NHEADS, BN), 256, ATTN_SMEM_BYTES>>>();
    proj2_kernel<<<BN * NN / 16, 256>>>(Wo, ao);
    attn_m<4, 2><<<dim3(NN / 128, 4, BN), 256, ATTN_SMEM_BYTES>>>();
    combine2_kernel<<<BN * NN * 16 / 256, 256>>>(out);
}